// round 1
// baseline (speedup 1.0000x reference)
#include <cuda_runtime.h>

// ---------------------------------------------------------------------------
// Scratch: __device__ globals (no allocation allowed anywhere).
// ---------------------------------------------------------------------------
__device__ float g_enc1[128*256*484];     // (B,256,22,22)
__device__ float g_enc2[128*512*400];     // (B,512,20,20)
__device__ float g_pool[128*512*100];     // (B,512,10,10)
__device__ float g_enc3[128*1024*64];     // (B,1024,8,8)
__device__ float g_hfeat[128*64*9];       // (B,64,3,3)
__device__ float g_ih1[128*64*144];       // (B,64,12,12)
__device__ float g_ih2[128*128*36];       // (B,128,6,6)
__device__ float g_es1[128*1024];
__device__ float g_concat[128*1024];      // [es2 | ih_fc]
__device__ float g_wb[128*2056];
__device__ float g_cpart[27*1024*1024];   // conv split-K partials
__device__ float g_fpart[4*1024*1024];    // fc split-K partials

// ---------------------------------------------------------------------------
// FC GEMM: C[m,n] = sum_k A[m,k] * W[n,k]   (A: 128xK row-major, W: NxK row-major)
// M == 128 (one M tile). grid = (ceil(N/128), 1, S). Writes partial[s][m][n].
// 256 threads, 128x128 tile, 8x8 microtile, K chunk 8.
// ---------------------------------------------------------------------------
__global__ __launch_bounds__(256) void fc_gemm(
    const float* __restrict__ A, const float* __restrict__ W,
    float* __restrict__ part, int N, int K, int Ksplit)
{
    const int tid  = threadIdx.x;
    const int n0   = blockIdx.x * 128;
    const int s    = blockIdx.z;
    const int kbeg = s * Ksplit;
    const int kend = kbeg + Ksplit;

    __shared__ __align__(16) float As[8*132];
    __shared__ __align__(16) float Ws[8*132];

    const int row = tid >> 1;           // 0..127  (m for A, n-local for W)
    const int kl  = (tid & 1) * 4;      // 0 or 4
    const bool nval = (n0 + row) < N;

    const float* Ap = A + (size_t)row * K;
    const float* Wp = W + (size_t)(nval ? (n0 + row) : 0) * K;

    const int ty = tid >> 4, tx = tid & 15;
    float acc[8][8];
#pragma unroll
    for (int i = 0; i < 8; i++)
#pragma unroll
        for (int j = 0; j < 8; j++) acc[i][j] = 0.f;

    for (int kb = kbeg; kb < kend; kb += 8) {
        float4 av = *(const float4*)(Ap + kb + kl);
        float4 wv = nval ? *(const float4*)(Wp + kb + kl) : make_float4(0.f,0.f,0.f,0.f);
        __syncthreads();
        As[(kl+0)*132 + row] = av.x; As[(kl+1)*132 + row] = av.y;
        As[(kl+2)*132 + row] = av.z; As[(kl+3)*132 + row] = av.w;
        Ws[(kl+0)*132 + row] = wv.x; Ws[(kl+1)*132 + row] = wv.y;
        Ws[(kl+2)*132 + row] = wv.z; Ws[(kl+3)*132 + row] = wv.w;
        __syncthreads();
#pragma unroll
        for (int kk = 0; kk < 8; kk++) {
            float4 a0 = *(const float4*)&As[kk*132 + ty*8];
            float4 a1 = *(const float4*)&As[kk*132 + ty*8 + 4];
            float4 b0 = *(const float4*)&Ws[kk*132 + tx*8];
            float4 b1 = *(const float4*)&Ws[kk*132 + tx*8 + 4];
            float a[8] = {a0.x,a0.y,a0.z,a0.w,a1.x,a1.y,a1.z,a1.w};
            float b[8] = {b0.x,b0.y,b0.z,b0.w,b1.x,b1.y,b1.z,b1.w};
#pragma unroll
            for (int i = 0; i < 8; i++)
#pragma unroll
                for (int j = 0; j < 8; j++) acc[i][j] += a[i]*b[j];
        }
    }

#pragma unroll
    for (int i = 0; i < 8; i++) {
        int m = ty*8 + i;
        float* pp = part + ((size_t)s*128 + m) * N + n0;
#pragma unroll
        for (int j = 0; j < 8; j++) {
            int nl = tx*8 + j;
            if (n0 + nl < N) pp[nl] = acc[i][j];
        }
    }
}

// fc epilogue: out[m*ldout + n] = act( bias[n] + sum_s part[s][m][n] )
__global__ void fc_epi(const float* __restrict__ part, const float* __restrict__ bias,
                       float* __restrict__ out, int N, int S, int ldout, int relu)
{
    int idx = blockIdx.x * blockDim.x + threadIdx.x;
    if (idx >= 128 * N) return;
    int m = idx / N, n = idx - m * N;
    float v = bias[n];
    for (int s = 0; s < S; s++) v += part[((size_t)s*128 + m) * N + n];
    if (relu) v = fmaxf(v, 0.f);
    out[(size_t)m * ldout + n] = v;
}

// ---------------------------------------------------------------------------
// Implicit-GEMM conv (pad=0, runtime stride, 3x3). NCHW in, weights (Cout,Cin,3,3).
// GEMM: M = B*OH*OW (multiple of 128), N = Cout, K = Cin*9.
// grid = (ceil(N/128), M/128, S). Writes partial[s][m][n].
// ---------------------------------------------------------------------------
__global__ __launch_bounds__(256) void conv_gemm(
    const float* __restrict__ in, const float* __restrict__ w, float* __restrict__ part,
    int Cin, int H, int Wd, int Cout, int OH, int OW, int stride, int Ksplit)
{
    const int tid  = threadIdx.x;
    const int K    = Cin * 9;
    const int n0   = blockIdx.x * 128;
    const int m0   = blockIdx.y * 128;
    const int s    = blockIdx.z;
    const int M    = gridDim.y * 128;
    const int kbeg = s * Ksplit;
    const int kend = kbeg + Ksplit;

    __shared__ __align__(16) float As[8*132];
    __shared__ __align__(16) float Ws[8*132];

    // per-thread A pixel (fixed): m = m0 + (tid & 127)
    const int mm = tid & 127;
    const int m  = m0 + mm;
    const int P  = OH * OW;
    const int b  = m / P;
    const int p  = m - b * P;
    const int oh = p / OW;
    const int ow = p - oh * OW;
    const int HW = H * Wd;
    const float* inb = in + (size_t)b * Cin * HW + (oh * stride) * Wd + (ow * stride);
    const int kkbase = tid >> 7;   // 0 or 1

    const int nrow = tid >> 1;
    const int kl   = (tid & 1) * 4;
    const bool nval = (n0 + nrow) < Cout;
    const float* Wp = w + (size_t)(nval ? (n0 + nrow) : 0) * K;

    const int ty = tid >> 4, tx = tid & 15;
    float acc[8][8];
#pragma unroll
    for (int i = 0; i < 8; i++)
#pragma unroll
        for (int j = 0; j < 8; j++) acc[i][j] = 0.f;

    for (int kb = kbeg; kb < kend; kb += 8) {
        float areg[4];
#pragma unroll
        for (int i = 0; i < 4; i++) {
            int kg = kb + kkbase + 2*i;
            int ci = kg / 9;
            int r  = kg - 9*ci;
            int kh = r / 3;
            int kw = r - 3*kh;
            areg[i] = __ldg(inb + (size_t)ci*HW + kh*Wd + kw);
        }
        float4 wv = nval ? *(const float4*)(Wp + kb + kl) : make_float4(0.f,0.f,0.f,0.f);
        __syncthreads();
#pragma unroll
        for (int i = 0; i < 4; i++) As[(kkbase + 2*i)*132 + mm] = areg[i];
        Ws[(kl+0)*132 + nrow] = wv.x; Ws[(kl+1)*132 + nrow] = wv.y;
        Ws[(kl+2)*132 + nrow] = wv.z; Ws[(kl+3)*132 + nrow] = wv.w;
        __syncthreads();
#pragma unroll
        for (int kk = 0; kk < 8; kk++) {
            float4 a0 = *(const float4*)&As[kk*132 + ty*8];
            float4 a1 = *(const float4*)&As[kk*132 + ty*8 + 4];
            float4 b0 = *(const float4*)&Ws[kk*132 + tx*8];
            float4 b1 = *(const float4*)&Ws[kk*132 + tx*8 + 4];
            float a[8] = {a0.x,a0.y,a0.z,a0.w,a1.x,a1.y,a1.z,a1.w};
            float bb[8] = {b0.x,b0.y,b0.z,b0.w,b1.x,b1.y,b1.z,b1.w};
#pragma unroll
            for (int i = 0; i < 8; i++)
#pragma unroll
                for (int j = 0; j < 8; j++) acc[i][j] += a[i]*bb[j];
        }
    }

#pragma unroll
    for (int i = 0; i < 8; i++) {
        int mr = m0 + ty*8 + i;
        float* pp = part + ((size_t)s*M + mr) * Cout + n0;
#pragma unroll
        for (int j = 0; j < 8; j++) {
            int nl = tx*8 + j;
            if (n0 + nl < Cout) pp[nl] = acc[i][j];
        }
    }
}

// conv epilogue: reduce splits + bias + relu, pixel-major -> NCHW via smem transpose.
// grid = (ceil(P/32), Cout/32, B), 256 threads.
__global__ void conv_epi(const float* __restrict__ part, const float* __restrict__ bias,
                         float* __restrict__ out, int Cout, int P, int S, int M)
{
    __shared__ float t[32][33];
    const int b   = blockIdx.z;
    const int co0 = blockIdx.y * 32;
    const int p0  = blockIdx.x * 32;
    const int tid = threadIdx.x;
#pragma unroll
    for (int i = 0; i < 4; i++) {
        int e   = tid + 256*i;
        int col = e & 31;          // co-local (coalesced read dim)
        int pr  = e >> 5;          // p-local
        int p   = p0 + pr;
        float v = 0.f;
        if (p < P) {
            size_t base = ((size_t)b*P + p) * Cout + co0 + col;
            for (int s = 0; s < S; s++) v += part[(size_t)s*M*Cout + base];
        }
        t[col][pr] = v;
    }
    __syncthreads();
#pragma unroll
    for (int i = 0; i < 4; i++) {
        int e   = tid + 256*i;
        int pl  = e & 31;          // p-local (coalesced write dim)
        int col = e >> 5;
        int p   = p0 + pl;
        if (p < P) {
            float v = t[col][pl] + bias[co0 + col];
            out[((size_t)(b*Cout + co0 + col)) * P + p] = fmaxf(v, 0.f);
        }
    }
}

// ---------------------------------------------------------------------------
// Small direct kernels
// ---------------------------------------------------------------------------
// in_hand conv1: (B,1,24,24) -> (B,64,12,12), 3x3 s2 p1, relu.  grid=B
__global__ __launch_bounds__(256) void ih1_k(const float* __restrict__ patch,
    const float* __restrict__ w, const float* __restrict__ bias, float* __restrict__ out)
{
    __shared__ float img[576];
    __shared__ float wsm[576];
    const int b = blockIdx.x, tid = threadIdx.x;
    for (int i = tid; i < 576; i += 256) img[i] = patch[(size_t)b*1152 + 576 + i];
    for (int i = tid; i < 576; i += 256) wsm[i] = w[i];
    __syncthreads();
    for (int o = tid; o < 64*144; o += 256) {
        int co = o / 144, p = o - co*144;
        int oh = p / 12, ow = p - oh*12;
        float acc = bias[co];
#pragma unroll
        for (int kh = 0; kh < 3; kh++) {
            int ih = 2*oh - 1 + kh;
            if (ih < 0 || ih >= 24) continue;
#pragma unroll
            for (int kw = 0; kw < 3; kw++) {
                int iw = 2*ow - 1 + kw;
                if (iw < 0 || iw >= 24) continue;
                acc += img[ih*24 + iw] * wsm[co*9 + kh*3 + kw];
            }
        }
        out[((size_t)b*64 + co)*144 + p] = fmaxf(acc, 0.f);
    }
}

// in_hand conv2: (B,64,12,12) -> (B,128,6,6), 3x3 s2 p1, relu.  grid=B
__global__ __launch_bounds__(256) void ih2_k(const float* __restrict__ in,
    const float* __restrict__ w, const float* __restrict__ bias, float* __restrict__ out)
{
    __shared__ float img[64*144];
    const int b = blockIdx.x, tid = threadIdx.x;
    for (int i = tid; i < 64*144; i += 256) img[i] = in[(size_t)b*64*144 + i];
    __syncthreads();
    for (int o = tid; o < 128*36; o += 256) {
        int co = o / 36, p = o - co*36;
        int oh = p / 6, ow = p - oh*6;
        float acc = bias[co];
        for (int ci = 0; ci < 64; ci++) {
            const float* ip = img + ci*144;
            const float* wp = w + ((size_t)co*64 + ci)*9;
#pragma unroll
            for (int kh = 0; kh < 3; kh++) {
                int ih = 2*oh - 1 + kh;
                if (ih < 0 || ih >= 12) continue;
#pragma unroll
                for (int kw = 0; kw < 3; kw++) {
                    int iw = 2*ow - 1 + kw;
                    if (iw < 0 || iw >= 12) continue;
                    acc += ip[ih*12 + iw] * __ldg(wp + kh*3 + kw);
                }
            }
        }
        out[((size_t)b*128 + co)*36 + p] = fmaxf(acc, 0.f);
    }
}

// enc conv1: (B,1,24,24) -> (B,256,22,22), 3x3 s1 p0, relu.  grid=(B, 4) (64 co each)
__global__ __launch_bounds__(256) void enc1_k(const float* __restrict__ patch,
    const float* __restrict__ w, const float* __restrict__ bias, float* __restrict__ out)
{
    __shared__ float img[576];
    __shared__ float wsm[576];
    const int b = blockIdx.x, co0 = blockIdx.y * 64, tid = threadIdx.x;
    for (int i = tid; i < 576; i += 256) img[i] = patch[(size_t)b*1152 + i];
    for (int i = tid; i < 576; i += 256) wsm[i] = w[(size_t)co0*9 + i];
    __syncthreads();
    for (int o = tid; o < 64*484; o += 256) {
        int col = o / 484, p = o - col*484;
        int oh = p / 22, ow = p - oh*22;
        float acc = bias[co0 + col];
#pragma unroll
        for (int kh = 0; kh < 3; kh++)
#pragma unroll
            for (int kw = 0; kw < 3; kw++)
                acc += img[(oh+kh)*24 + ow + kw] * wsm[col*9 + kh*3 + kw];
        out[((size_t)b*256 + co0 + col)*484 + p] = fmaxf(acc, 0.f);
    }
}

// maxpool 2x2: (B,512,20,20) -> (B,512,10,10)
__global__ void pool_k(const float* __restrict__ in, float* __restrict__ out)
{
    int idx = blockIdx.x * blockDim.x + threadIdx.x;
    if (idx >= 128*512*100) return;
    int p = idx % 100, c = idx / 100;
    int oh = p / 10, ow = p - oh*10;
    const float* ip = in + (size_t)c*400 + (oh*2)*20 + ow*2;
    float v = fmaxf(fmaxf(ip[0], ip[1]), fmaxf(ip[20], ip[21]));
    out[idx] = v;
}

// ---------------------------------------------------------------------------
// Final fused stage. Block per batch.
// T[c,d,g] = sum_{e,h,w} basis[c,d,e,h,w]*hf[g*8+e,h,w]
// out[f*8+d] = dbias[f] + sum_{c,g} coeff[f,g,c]*T[c,d,g]; feat=relu(out)
// x[j] = c2_b[j] + sum_i feat[i]*c2_w[j,i]
// ---------------------------------------------------------------------------
__global__ __launch_bounds__(256) void final_k(
    const float* __restrict__ hfeat, const float* __restrict__ wb,
    const float* __restrict__ basis, const float* __restrict__ c2w,
    const float* __restrict__ c2b, float* __restrict__ out)
{
    __shared__ float hf[576];
    __shared__ float coef[2048];
    __shared__ float T[2048];
    __shared__ float feat[64];
    __shared__ float db[8];
    const int b = blockIdx.x, tid = threadIdx.x;
    for (int i = tid; i < 576; i += 256)  hf[i]   = hfeat[(size_t)b*576 + i];
    for (int i = tid; i < 2048; i += 256) coef[i] = wb[(size_t)b*2056 + i];
    if (tid < 8) db[tid] = wb[(size_t)b*2056 + 2048 + tid];
    __syncthreads();
    for (int i = tid; i < 2048; i += 256) {
        int c = i >> 6, d = (i >> 3) & 7, g = i & 7;
        const float* bs = basis + (size_t)((c*8 + d)*8)*9;
        float acc = 0.f;
#pragma unroll
        for (int e = 0; e < 8; e++) {
            const float* hp = hf + (g*8 + e)*9;
#pragma unroll
            for (int q = 0; q < 9; q++) acc += __ldg(bs + e*9 + q) * hp[q];
        }
        T[i] = acc;
    }
    __syncthreads();
    if (tid < 64) {
        int f = tid >> 3, d = tid & 7;
        float acc = db[f];
        for (int c = 0; c < 32; c++) {
#pragma unroll
            for (int g = 0; g < 8; g++)
                acc += coef[(f*8 + g)*32 + c] * T[(c*8 + d)*8 + g];
        }
        feat[tid] = fmaxf(acc, 0.f);
    }
    __syncthreads();
    if (tid < 16) {
        float acc = c2b[tid];
#pragma unroll
        for (int i = 0; i < 64; i++) acc += feat[i] * __ldg(c2w + tid*64 + i);
        out[b*16 + tid] = acc;
    }
}

// ---------------------------------------------------------------------------
extern "C" void kernel_launch(void* const* d_in, const int* in_sizes, int n_in,
                              void* d_out, int out_size)
{
    const float* obs    = (const float*)d_in[0];
    const float* patch  = (const float*)d_in[1];
    const float* enc_w1 = (const float*)d_in[2];
    const float* enc_b1 = (const float*)d_in[3];
    const float* enc_w2 = (const float*)d_in[4];
    const float* enc_b2 = (const float*)d_in[5];
    const float* enc_w3 = (const float*)d_in[6];
    const float* enc_b3 = (const float*)d_in[7];
    const float* pc_w   = (const float*)d_in[8];
    const float* pc_b   = (const float*)d_in[9];
    const float* es_w1  = (const float*)d_in[10];
    const float* es_b1  = (const float*)d_in[11];
    const float* es_w2  = (const float*)d_in[12];
    const float* es_b2  = (const float*)d_in[13];
    const float* ih_w1  = (const float*)d_in[14];
    const float* ih_b1  = (const float*)d_in[15];
    const float* ih_w2  = (const float*)d_in[16];
    const float* ih_b2  = (const float*)d_in[17];
    const float* ihfc_w = (const float*)d_in[18];
    const float* ihfc_b = (const float*)d_in[19];
    const float* df_w   = (const float*)d_in[20];
    const float* df_b   = (const float*)d_in[21];
    const float* basis  = (const float*)d_in[22];
    const float* c2_w   = (const float*)d_in[23];
    const float* c2_b   = (const float*)d_in[24];
    float* out = (float*)d_out;

    float *enc1, *enc2, *pool, *enc3, *hfeat, *ih1, *ih2, *es1, *concat, *wb, *cpart, *fpart;
    cudaGetSymbolAddress((void**)&enc1,  g_enc1);
    cudaGetSymbolAddress((void**)&enc2,  g_enc2);
    cudaGetSymbolAddress((void**)&pool,  g_pool);
    cudaGetSymbolAddress((void**)&enc3,  g_enc3);
    cudaGetSymbolAddress((void**)&hfeat, g_hfeat);
    cudaGetSymbolAddress((void**)&ih1,   g_ih1);
    cudaGetSymbolAddress((void**)&ih2,   g_ih2);
    cudaGetSymbolAddress((void**)&es1,   g_es1);
    cudaGetSymbolAddress((void**)&concat,g_concat);
    cudaGetSymbolAddress((void**)&wb,    g_wb);
    cudaGetSymbolAddress((void**)&cpart, g_cpart);
    cudaGetSymbolAddress((void**)&fpart, g_fpart);

    // ---- FC / in-hand path ----
    ih1_k<<<128, 256>>>(patch, ih_w1, ih_b1, ih1);
    ih2_k<<<128, 256>>>(ih1, ih_w2, ih_b2, ih2);
    // ih_fc: (128,4608)->(128,512), relu, -> concat[:,512:]
    fc_gemm<<<dim3(4,1,16), 256>>>(ih2, ihfc_w, fpart, 512, 4608, 288);
    fc_epi<<<(128*512 + 255)/256, 256>>>(fpart, ihfc_b, concat + 512, 512, 16, 1024, 1);
    // es1: (128,16384)->(128,1024), relu
    fc_gemm<<<dim3(8,1,16), 256>>>(obs, es_w1, fpart, 1024, 16384, 1024);
    fc_epi<<<(128*1024 + 255)/256, 256>>>(fpart, es_b1, es1, 1024, 16, 1024, 1);
    // es2: (128,1024)->(128,512), relu, -> concat[:,:512]
    fc_gemm<<<dim3(4,1,8), 256>>>(es1, es_w2, fpart, 512, 1024, 128);
    fc_epi<<<(128*512 + 255)/256, 256>>>(fpart, es_b2, concat, 512, 8, 1024, 1);
    // df: (128,1024)->(128,2056), NO relu
    fc_gemm<<<dim3(17,1,8), 256>>>(concat, df_w, fpart, 2056, 1024, 128);
    fc_epi<<<(128*2056 + 255)/256, 256>>>(fpart, df_b, wb, 2056, 8, 2056, 0);

    // ---- encoder conv path ----
    enc1_k<<<dim3(128,4), 256>>>(patch, enc_w1, enc_b1, enc1);
    // conv2: 256->512, 22->20, s1.  M=51200, N=512, K=2304
    conv_gemm<<<dim3(4,400,1), 256>>>(enc1, enc_w2, cpart, 256, 22, 22, 512, 20, 20, 1, 2304);
    conv_epi<<<dim3(13,16,128), 256>>>(cpart, enc_b2, enc2, 512, 400, 1, 51200);
    pool_k<<<(128*512*100 + 255)/256, 256>>>(enc2, pool);
    // conv3: 512->1024, 10->8, s1.  M=8192, N=1024, K=4608
    conv_gemm<<<dim3(8,64,1), 256>>>(pool, enc_w3, cpart, 512, 10, 10, 1024, 8, 8, 1, 4608);
    conv_epi<<<dim3(2,32,128), 256>>>(cpart, enc_b3, enc3, 1024, 64, 1, 8192);
    // pc: 1024->64, 8->3, s2.  M=1152, N=64, K=9216, split-K=16
    conv_gemm<<<dim3(1,9,16), 256>>>(enc3, pc_w, cpart, 1024, 8, 8, 64, 3, 3, 2, 576);
    conv_epi<<<dim3(1,2,128), 256>>>(cpart, pc_b, hfeat, 64, 9, 16, 1152);

    // ---- fused final stage ----
    final_k<<<128, 256>>>(hfeat, wb, basis, c2_w, c2_b, out);
}